// round 1
// baseline (speedup 1.0000x reference)
#include <cuda_runtime.h>
#include <cuda_bf16.h>
#include <math.h>

// Problem shape (fixed by the reference):
//   emissions: (B=128, S=256, C=64) f32
//   true_tags: (B, S) i32
//   mask:      (B, S) f32 (all ones in this dataset, general code kept)
//   U:         (C, C) f32
// Output: scalar f32 = mean_b( free_energy[b] - path_energy[b] )

#define Bc 128
#define Sc 256
#define Cc 64

__device__ float g_batch_res[Bc];

__global__ __launch_bounds__(Cc, 1)
void crf_forward_kernel(const float* __restrict__ em,
                        const int*   __restrict__ tags,
                        const float* __restrict__ mask,
                        const float* __restrict__ U)
{
    const int b = blockIdx.x;
    const int j = threadIdx.x;          // tag index owned by this thread

    __shared__ float qbuf[2][Cc];
    __shared__ float sU[Cc * Cc];       // raw U (for path energy + generic mask path)
    __shared__ float red[Cc];

    // Stage raw U into smem (coalesced) and build this thread's expU column in regs.
    for (int i = j; i < Cc * Cc; i += Cc) sU[i] = U[i];

    float rExpU[Cc];
#pragma unroll
    for (int i = 0; i < Cc; ++i) rExpU[i] = __expf(U[i * Cc + j]);

    const float* emb   = em   + (size_t)b * Sc * Cc;
    const float* mb    = mask + (size_t)b * Sc;
    const int*   tagsb = tags + (size_t)b * Sc;

    // alpha0 = emissions[:,0,:]  ->  q(0) = exp(alpha0)
    qbuf[0][j] = __expf(emb[j]);
    int K = 0;                           // accumulated power-of-two exponent
    __syncthreads();

    // Software prefetch of step t=1 operands
    float emj = emb[Cc + j];
    float m   = mb[1];

    for (int t = 1; t < Sc; ++t) {
        // prefetch next step
        float emj_next = 0.0f, m_next = 1.0f;
        if (t + 1 < Sc) {
            emj_next = emb[(t + 1) * Cc + j];
            m_next   = mb[t + 1];
        }

        const float* qo = qbuf[(t - 1) & 1];

        // Load full q vector (broadcast-friendly; vectorized)
        float4 rq[Cc / 4];
#pragma unroll
        for (int i = 0; i < Cc / 4; ++i)
            rq[i] = reinterpret_cast<const float4*>(qo)[i];

        // Power-of-two renormalization from q[0] (identical across threads)
        float q0 = rq[0].x;
        int   k  = (int)((__float_as_uint(q0) >> 23) & 0xFF) - 127;
        float scale = __uint_as_float((unsigned)(127 - k) << 23);
        K += k;

        float s;
        if (m == 1.0f) {
            float s0 = 0.f, s1 = 0.f, s2 = 0.f, s3 = 0.f;
#pragma unroll
            for (int i = 0; i < Cc / 4; ++i) {
                s0 = fmaf(rq[i].x, rExpU[4 * i + 0], s0);
                s1 = fmaf(rq[i].y, rExpU[4 * i + 1], s1);
                s2 = fmaf(rq[i].z, rExpU[4 * i + 2], s2);
                s3 = fmaf(rq[i].w, rExpU[4 * i + 3], s3);
            }
            s = ((s0 + s1) + (s2 + s3)) * __expf(emj);
        } else if (m == 0.0f) {
            // te == 0 -> alpha_new[j] = LSE_i(alpha_i) for all j: s = sum(q)
            float s0 = 0.f, s1 = 0.f, s2 = 0.f, s3 = 0.f;
#pragma unroll
            for (int i = 0; i < Cc / 4; ++i) {
                s0 += rq[i].x; s1 += rq[i].y; s2 += rq[i].z; s3 += rq[i].w;
            }
            s = (s0 + s1) + (s2 + s3);
        } else {
            // generic fractional mask (never taken in this dataset)
            float acc = 0.f;
            const float* qof = qo;
            for (int i = 0; i < Cc; ++i)
                acc += qof[i] * __expf((emj + sU[i * Cc + j]) * m);
            s = acc;
        }

        qbuf[t & 1][j] = s * scale;
        __syncthreads();   // single barrier per step (double buffer)

        emj = emj_next;
        m   = m_next;
    }

    // ---- free energy: log(sum q_last) + K*ln2 ----
    // ---- path energy: emission-tag term + transition term ----
    float pe = 0.0f;
    for (int t = j; t < Sc; t += Cc) {
        float mt = mb[t];
        int   tg = tagsb[t];
        int   tm = (int)((float)tg * mt);      // tags_m = int(tag * mask)
        pe += emb[t * Cc + tm] * mt;
    }
    for (int t = 1 + j; t < Sc; t += Cc) {
        pe += sU[tagsb[t - 1] * Cc + tagsb[t]] * mb[t];
    }
    red[j] = pe;
    __syncthreads();

    if (j == 0) {
        const float* ql = qbuf[(Sc - 1) & 1];
        float qs = 0.0f;
#pragma unroll
        for (int i = 0; i < Cc; ++i) qs += ql[i];
        float free_e = logf(qs) + (float)K * 0.6931471805599453f;

        float pes = 0.0f;
#pragma unroll
        for (int i = 0; i < Cc; ++i) pes += red[i];

        g_batch_res[b] = free_e - pes;
    }
}

__global__ void crf_finalize_kernel(float* __restrict__ out)
{
    // tiny deterministic reduction
    if (threadIdx.x == 0) {
        float s = 0.0f;
#pragma unroll
        for (int i = 0; i < Bc; ++i) s += g_batch_res[i];
        out[0] = s / (float)Bc;
    }
}

extern "C" void kernel_launch(void* const* d_in, const int* in_sizes, int n_in,
                              void* d_out, int out_size)
{
    const float* emissions = (const float*)d_in[0];
    const int*   true_tags = (const int*)  d_in[1];
    const float* mask      = (const float*)d_in[2];
    const float* U         = (const float*)d_in[3];
    float* out = (float*)d_out;

    crf_forward_kernel<<<Bc, Cc>>>(emissions, true_tags, mask, U);
    crf_finalize_kernel<<<1, 32>>>(out);
}

// round 2
// speedup vs baseline: 1.1524x; 1.1524x over previous
#include <cuda_runtime.h>
#include <cuda_bf16.h>
#include <math.h>

// ChainCRF: B=128, S=256, C=64.
// One CTA (64 threads) per batch row; linear-domain forward recursion with
// power-of-two renormalization; log taken once at the end.
// Hot loop: packed fma.rn.f32x2 dot products, exp() prefetched off-chain,
// single __syncthreads per step.

#define Bc 128
#define Sc 256
#define Cc 64

__device__ float g_batch_res[Bc];

#define FMA2(d, a, b, c) \
    asm("fma.rn.f32x2 %0, %1, %2, %3;" : "=l"(d) : "l"(a), "l"(b), "l"(c))
#define ADD2(d, a, b) \
    asm("add.rn.f32x2 %0, %1, %2;" : "=l"(d) : "l"(a), "l"(b))
#define PACK2(d, lo, hi) \
    asm("mov.b64 %0, {%1, %2};" : "=l"(d) : "f"(lo), "f"(hi))
#define UNPACK2(lo, hi, s) \
    asm("mov.b64 {%0, %1}, %2;" : "=f"(lo), "=f"(hi) : "l"(s))

__global__ __launch_bounds__(Cc, 1)
void crf_forward_kernel(const float* __restrict__ em,
                        const int*   __restrict__ tags,
                        const float* __restrict__ mask,
                        const float* __restrict__ U)
{
    const int b = blockIdx.x;
    const int j = threadIdx.x;          // tag owned by this thread

    __shared__ __align__(16) float qbuf0[Cc];
    __shared__ __align__(16) float qbuf1[Cc];
    __shared__ float sU[Cc * Cc];       // raw U for path energy + generic path
    __shared__ float red[Cc];

    // Stage raw U (coalesced) and build this thread's packed expU column.
    for (int i = j; i < Cc * Cc; i += Cc) sU[i] = U[i];

    unsigned long long rE[Cc / 2];      // rE[i] = { expU[2i][j], expU[2i+1][j] }
#pragma unroll
    for (int i = 0; i < Cc / 2; ++i) {
        float e0 = __expf(U[(2 * i + 0) * Cc + j]);
        float e1 = __expf(U[(2 * i + 1) * Cc + j]);
        PACK2(rE[i], e0, e1);
    }

    const float* emb   = em   + (size_t)b * Sc * Cc;
    const float* mb    = mask + (size_t)b * Sc;
    const int*   tagsb = tags + (size_t)b * Sc;

    // Uniform-mask check (hoists the branch out of the hot loop).
    int ok = 1;
    for (int t = j; t < Sc; t += Cc) ok &= (mb[t] == 1.0f);
    const int allone = __syncthreads_and(ok);

    // q(0) = exp(alpha0) = exp(emissions[:,0,:])
    qbuf0[j] = __expf(emb[j]);
    int K = 0;
    __syncthreads();

    if (allone) {
        // ---------------- fast branch-free loop ----------------
        float emx_cur = __expf(emb[Cc + j]);                 // exp(em[t=1][j])
        float em_next = (Sc > 2) ? emb[2 * Cc + j] : 0.0f;   // raw em[t=2][j]

        const float* qr = qbuf0;
        float*       qw = qbuf1;

#pragma unroll 2
        for (int t = 1; t < Sc; ++t) {
            // distance-2 prefetch of raw emissions (off-chain)
            float em_next2 = 0.0f;
            if (t + 2 < Sc) em_next2 = emb[(t + 2) * Cc + j];

            // load q (packed pairs)
            unsigned long long qp[Cc / 2];
#pragma unroll
            for (int i = 0; i < Cc / 4; ++i) {
                ulonglong2 v = reinterpret_cast<const ulonglong2*>(qr)[i];
                qp[2 * i + 0] = v.x;
                qp[2 * i + 1] = v.y;
            }

            // power-of-two renorm from q[0] (uniform across threads);
            // folded into the emission multiplier -> off the critical chain
            float q0, q1_unused;
            UNPACK2(q0, q1_unused, qp[0]);
            int k = (int)((__float_as_uint(q0) >> 23) & 0xFF) - 127;
            K += k;
            emx_cur *= __uint_as_float((unsigned)(127 - k) << 23);

            // next step's exp, off-chain (MUFU hidden under the FMA tree)
            float emx_next = __expf(em_next);

            // packed dot product: 32 x fma.rn.f32x2, 4 accumulators
            unsigned long long a0 = 0ull, a1 = 0ull, a2 = 0ull, a3 = 0ull;
#pragma unroll
            for (int i = 0; i < Cc / 8; ++i) {
                FMA2(a0, qp[4 * i + 0], rE[4 * i + 0], a0);
                FMA2(a1, qp[4 * i + 1], rE[4 * i + 1], a1);
                FMA2(a2, qp[4 * i + 2], rE[4 * i + 2], a2);
                FMA2(a3, qp[4 * i + 3], rE[4 * i + 3], a3);
            }
            ADD2(a0, a0, a1);
            ADD2(a2, a2, a3);
            ADD2(a0, a0, a2);
            float lo, hi;
            UNPACK2(lo, hi, a0);

            qw[j] = (lo + hi) * emx_cur;
            __syncthreads();

            emx_cur = emx_next;
            em_next = em_next2;
            const float* tr = qr; qr = qw; qw = const_cast<float*>(tr);
        }

        // stash final q pointer parity via copy so epilogue can read it
        if (((Sc - 1) & 1) == 1) { /* last write was qbuf1 when Sc-1 odd */ }
    } else {
        // ---------------- generic (masked) fallback ----------------
        float emj = emb[Cc + j];
        float m   = mb[1];
        const float* qr = qbuf0;
        float*       qw = qbuf1;
        for (int t = 1; t < Sc; ++t) {
            float emj_next = 0.0f, m_next = 1.0f;
            if (t + 1 < Sc) { emj_next = emb[(t + 1) * Cc + j]; m_next = mb[t + 1]; }

            float q0 = qr[0];
            int   k  = (int)((__float_as_uint(q0) >> 23) & 0xFF) - 127;
            float scale = __uint_as_float((unsigned)(127 - k) << 23);
            K += k;

            float s;
            if (m == 1.0f) {
                float acc = 0.0f;
                for (int i = 0; i < Cc; ++i)
                    acc = fmaf(qr[i], __expf(sU[i * Cc + j]), acc);
                s = acc * __expf(emj);
            } else if (m == 0.0f) {
                float acc = 0.0f;
                for (int i = 0; i < Cc; ++i) acc += qr[i];
                s = acc;
            } else {
                float acc = 0.0f;
                for (int i = 0; i < Cc; ++i)
                    acc += qr[i] * __expf((emj + sU[i * Cc + j]) * m);
                s = acc;
            }
            qw[j] = s * scale;
            __syncthreads();
            emj = emj_next; m = m_next;
            float* tr = const_cast<float*>(qr); qr = qw; qw = tr;
        }
    }

    // ---- path energy (emission-tag + transition terms) ----
    float pe = 0.0f;
    for (int t = j; t < Sc; t += Cc) {
        float mt = mb[t];
        int   tg = tagsb[t];
        int   tm = (int)((float)tg * mt);
        pe += emb[t * Cc + tm] * mt;
    }
    for (int t = 1 + j; t < Sc; t += Cc) {
        pe += sU[tagsb[t - 1] * Cc + tagsb[t]] * mb[t];
    }
    red[j] = pe;
    __syncthreads();

    if (j == 0) {
        // q_{S-1} lives in qbuf1 when (Sc-1) is odd, qbuf0 otherwise
        const float* ql = (((Sc - 1) & 1) == 1) ? qbuf1 : qbuf0;
        float qs = 0.0f;
#pragma unroll
        for (int i = 0; i < Cc; ++i) qs += ql[i];
        float free_e = logf(qs) + (float)K * 0.6931471805599453f;

        float pes = 0.0f;
#pragma unroll
        for (int i = 0; i < Cc; ++i) pes += red[i];

        g_batch_res[b] = free_e - pes;
    }
}

__global__ void crf_finalize_kernel(float* __restrict__ out)
{
    const int i = threadIdx.x;          // 128 threads
    float v = g_batch_res[i];
#pragma unroll
    for (int o = 16; o > 0; o >>= 1)
        v += __shfl_down_sync(0xFFFFFFFFu, v, o);

    __shared__ float w[4];
    if ((i & 31) == 0) w[i >> 5] = v;
    __syncthreads();
    if (i == 0) out[0] = (w[0] + w[1] + w[2] + w[3]) * (1.0f / (float)Bc);
}

extern "C" void kernel_launch(void* const* d_in, const int* in_sizes, int n_in,
                              void* d_out, int out_size)
{
    const float* emissions = (const float*)d_in[0];
    const int*   true_tags = (const int*)  d_in[1];
    const float* mask      = (const float*)d_in[2];
    const float* U         = (const float*)d_in[3];
    float* out = (float*)d_out;

    crf_forward_kernel<<<Bc, Cc>>>(emissions, true_tags, mask, U);
    crf_finalize_kernel<<<1, Bc>>>(out);
}

// round 3
// speedup vs baseline: 1.1659x; 1.0117x over previous
#include <cuda_runtime.h>
#include <cuda_bf16.h>
#include <math.h>

// ChainCRF: B=128, S=256, C=64.
// One CTA (128 threads) per batch row. Linear-domain forward recursion with
// power-of-two renormalization; log taken once at the end.
// Thread pair (2j, 2j+1) owns tag j: each computes half the 64-length dot
// (16 fma.rn.f32x2), combined with one intra-warp shfl.bfly.
// Finalize fused: last CTA (atomic ticket) reduces the batch mean.

#define Bc 128
#define Sc 256
#define Cc 64
#define Tc 128

__device__ float g_batch_res[Bc];
__device__ unsigned int g_ticket = 0;

#define FMA2(d, a, b, c) \
    asm("fma.rn.f32x2 %0, %1, %2, %3;" : "=l"(d) : "l"(a), "l"(b), "l"(c))
#define ADD2(d, a, b) \
    asm("add.rn.f32x2 %0, %1, %2;" : "=l"(d) : "l"(a), "l"(b))
#define PACK2(d, lo, hi) \
    asm("mov.b64 %0, {%1, %2};" : "=l"(d) : "f"(lo), "f"(hi))
#define UNPACK2(lo, hi, s) \
    asm("mov.b64 {%0, %1}, %2;" : "=f"(lo), "=f"(hi) : "l"(s))

// q layout: q[0..31] at [0..31], q[32..63] at [36..67] (4-float skew kills the
// 2-way bank conflict between the two half-range broadcast reads).
__device__ __forceinline__ int padpos(int i) { return i + ((i >> 5) << 2); }

__global__ __launch_bounds__(Tc, 1)
void crf_kernel(const float* __restrict__ em,
                const int*   __restrict__ tags,
                const float* __restrict__ mask,
                const float* __restrict__ U,
                float* __restrict__ out)
{
    const int b   = blockIdx.x;
    const int tid = threadIdx.x;
    const int j   = tid >> 1;        // tag owned by this pair
    const int h   = tid & 1;         // which half of the i-range

    __shared__ __align__(16) float qA[68];
    __shared__ __align__(16) float qB[68];
    __shared__ float sU[Cc * Cc];
    __shared__ float red[Tc];

    // Stage raw U (coalesced) — used by path energy + generic fallback.
    for (int i = tid; i < Cc * Cc; i += Tc) sU[i] = U[i];

    // This thread's expU half-column, packed in pairs over i.
    // rE[2c] = {expU[base+4c][j], expU[base+4c+1][j]}, rE[2c+1] = next two.
    const int base = 32 * h;
    unsigned long long rE[16];
#pragma unroll
    for (int c = 0; c < 8; ++c) {
        int i0 = base + 4 * c;
        float e0 = __expf(U[(i0 + 0) * Cc + j]);
        float e1 = __expf(U[(i0 + 1) * Cc + j]);
        float e2 = __expf(U[(i0 + 2) * Cc + j]);
        float e3 = __expf(U[(i0 + 3) * Cc + j]);
        PACK2(rE[2 * c + 0], e0, e1);
        PACK2(rE[2 * c + 1], e2, e3);
    }

    const float* emb   = em   + (size_t)b * Sc * Cc;
    const float* mb    = mask + (size_t)b * Sc;
    const int*   tagsb = tags + (size_t)b * Sc;

    // Hoist the mask branch out of the hot loop.
    int ok = 1;
    for (int t = tid; t < Sc; t += Tc) ok &= (mb[t] == 1.0f);
    const int allone = __syncthreads_and(ok);

    // q(0) = exp(emissions[:,0,:])
    if (h == 0) qA[padpos(j)] = __expf(emb[j]);
    int K = 0;
    __syncthreads();

    const float* qr = qA;
    float*       qw = qB;

    if (allone) {
        // -------- fast branch-free loop --------
        float emx_cur = __expf(emb[Cc + j]);     // exp(em[1][j])
        float em_n1   = emb[2 * Cc + j];         // raw em[2][j]

#pragma unroll 2
        for (int t = 1; t < Sc; ++t) {
            // distance-2 prefetch of raw emissions (off-chain)
            float em_n2 = 0.0f;
            if (t + 2 < Sc) em_n2 = emb[(t + 2) * Cc + j];

            // load this half's 32 q values (8 x LDS.128, broadcast pairs)
            const float* src = qr + 36 * h;      // 144B offset: 16B-aligned
            unsigned long long qp[16];
#pragma unroll
            for (int c = 0; c < 8; ++c) {
                ulonglong2 v = reinterpret_cast<const ulonglong2*>(src)[c];
                qp[2 * c + 0] = v.x;
                qp[2 * c + 1] = v.y;
            }

            // power-of-two renorm from q[0] (uniform); folded into emission
            // multiplier early -> off the critical chain
            float q0s = qr[0];
            int   k   = (int)((__float_as_uint(q0s) >> 23) & 0xFF) - 127;
            K += k;
            float emx = emx_cur * __uint_as_float((unsigned)(127 - k) << 23);

            // next step's exp, hidden under the FMA tree
            float emx_next = __expf(em_n1);

            // half dot: 16 packed FMAs, 2 accumulators
            unsigned long long a0 = 0ull, a1 = 0ull;
#pragma unroll
            for (int c = 0; c < 8; ++c) {
                FMA2(a0, qp[2 * c + 0], rE[2 * c + 0], a0);
                FMA2(a1, qp[2 * c + 1], rE[2 * c + 1], a1);
            }
            ADD2(a0, a0, a1);
            float lo, hi;
            UNPACK2(lo, hi, a0);
            float sh = lo + hi;

            // combine the two halves inside the warp
            float s = (sh + __shfl_xor_sync(0xFFFFFFFFu, sh, 1)) * emx;

            if (h == 0) qw[padpos(j)] = s;
            __syncthreads();

            emx_cur = emx_next;
            em_n1   = em_n2;
            const float* tr = qr; qr = qw; qw = const_cast<float*>(tr);
        }
    } else {
        // -------- generic (masked) fallback — never taken in this dataset --------
        float emj = emb[Cc + j];
        float m   = mb[1];
        for (int t = 1; t < Sc; ++t) {
            float emj_next = 0.0f, m_next = 1.0f;
            if (t + 1 < Sc) { emj_next = emb[(t + 1) * Cc + j]; m_next = mb[t + 1]; }

            float q0s = qr[0];
            int   k   = (int)((__float_as_uint(q0s) >> 23) & 0xFF) - 127;
            float scale = __uint_as_float((unsigned)(127 - k) << 23);
            K += k;

            float s;
            if (m == 1.0f) {
                float acc = 0.0f;
                for (int i = 0; i < Cc; ++i)
                    acc = fmaf(qr[padpos(i)], __expf(sU[i * Cc + j]), acc);
                s = acc * __expf(emj);
            } else if (m == 0.0f) {
                float acc = 0.0f;
                for (int i = 0; i < Cc; ++i) acc += qr[padpos(i)];
                s = acc;
            } else {
                float acc = 0.0f;
                for (int i = 0; i < Cc; ++i)
                    acc += qr[padpos(i)] * __expf((emj + sU[i * Cc + j]) * m);
                s = acc;
            }
            if (h == 0) qw[padpos(j)] = s * scale;
            __syncthreads();
            emj = emj_next; m = m_next;
            const float* tr = qr; qr = qw; qw = const_cast<float*>(tr);
        }
    }

    // ---- path energy (emission-tag + transition terms) ----
    float pe = 0.0f;
    for (int t = tid; t < Sc; t += Tc) {
        float mt = mb[t];
        int   tg = tagsb[t];
        int   tm = (int)((float)tg * mt);
        pe += emb[t * Cc + tm] * mt;
    }
    for (int t = 1 + tid; t < Sc; t += Tc) {
        pe += sU[tagsb[t - 1] * Cc + tagsb[t]] * mb[t];
    }
    red[tid] = pe;
    __syncthreads();

    if (tid == 0) {
        // t=1..255 writes alternate qB,qA,...; 255 odd -> final q in qB
        const float* ql = (((Sc - 1) & 1) == 1) ? qB : qA;
        float qs = 0.0f;
#pragma unroll
        for (int i = 0; i < Cc; ++i) qs += ql[padpos(i)];
        float free_e = logf(qs) + (float)K * 0.6931471805599453f;

        float pes = 0.0f;
#pragma unroll
        for (int i = 0; i < Tc; ++i) pes += red[i];

        g_batch_res[b] = free_e - pes;

        // fused finalize: last CTA reduces the batch mean (deterministic:
        // fixed-order sum by one thread).
        __threadfence();
        unsigned int old = atomicAdd(&g_ticket, 1u);
        if (old == Bc - 1) {
            __threadfence();
            float ssum = 0.0f;
#pragma unroll
            for (int i = 0; i < Bc; ++i) ssum += g_batch_res[i];
            out[0] = ssum * (1.0f / (float)Bc);
            g_ticket = 0;   // reset for the next graph replay
        }
    }
}

extern "C" void kernel_launch(void* const* d_in, const int* in_sizes, int n_in,
                              void* d_out, int out_size)
{
    const float* emissions = (const float*)d_in[0];
    const int*   true_tags = (const int*)  d_in[1];
    const float* mask      = (const float*)d_in[2];
    const float* U         = (const float*)d_in[3];
    float* out = (float*)d_out;

    crf_kernel<<<Bc, Tc>>>(emissions, true_tags, mask, U, out);
}

// round 5
// speedup vs baseline: 1.3128x; 1.1260x over previous
#include <cuda_runtime.h>
#include <cuda_bf16.h>
#include <math.h>

// ChainCRF: B=128, S=256, C=64.
// ONE WARP per batch row (128 CTAs x 32 threads). Thread l owns tags 2l,2l+1.
// Linear-domain forward recursion, power-of-two renorm, log once at the end.
// Per step: 16 broadcast LDS.128 (q), 64 fma.rn.f32x2 (full 64x64 matvec),
// STS.64 + __syncwarp. No __syncthreads anywhere. expU lives in 128 registers.
// Emissions prefetched at distance 4-7; exp() one step ahead (off-chain).

#define Bc 128
#define Sc 256
#define Cc 64

__device__ float g_batch_res[Bc];
__device__ unsigned int g_ticket = 0;

#define FMA2(d,a,b,c)  asm("fma.rn.f32x2 %0, %1, %2, %3;" : "=l"(d) : "l"(a), "l"(b), "l"(c))
#define ADD2(d,a,b)    asm("add.rn.f32x2 %0, %1, %2;" : "=l"(d) : "l"(a), "l"(b))
#define MUL2(d,a,b)    asm("mul.rn.f32x2 %0, %1, %2;" : "=l"(d) : "l"(a), "l"(b))
#define PACK2(d,lo,hi) asm("mov.b64 %0, {%1, %2};" : "=l"(d) : "f"(lo), "f"(hi))
#define UNPACK2(lo,hi,s) asm("mov.b64 {%0, %1}, %2;" : "=f"(lo), "=f"(hi) : "l"(s))

#define EXPF2(d, v) do { float _ea = __expf((v).x); float _eb = __expf((v).y); \
                         PACK2(d, _ea, _eb); } while (0)

// One forward step: q_new[j] = (sum_i q_i * expU[i][j]) * emx[j] * scale
// QR/QW: 64-float smem buffers. EMX: u64 packed {emx_j0, emx_j1}.
#define STEP(QR, QW, EMX) do {                                                 \
    float _q0 = (QR)[0];                                                       \
    int   _k  = (int)((__float_as_uint(_q0) >> 23) & 0xFF) - 127;              \
    K += _k;                                                                   \
    float _sc = __uint_as_float((unsigned)(127 - _k) << 23);                   \
    unsigned long long _scp;  PACK2(_scp, _sc, _sc);                           \
    unsigned long long _emxs; MUL2(_emxs, (EMX), _scp);                        \
    unsigned long long _a0 = 0ull, _a1 = 0ull, _b0 = 0ull, _b1 = 0ull;         \
    const ulonglong2* _qv = (const ulonglong2*)(QR);                           \
    _Pragma("unroll")                                                          \
    for (int _c = 0; _c < 16; ++_c) {                                          \
        ulonglong2 _v = _qv[_c];                                               \
        FMA2(_a0, _v.x, rEa[2*_c+0], _a0);                                     \
        FMA2(_b0, _v.x, rEb[2*_c+0], _b0);                                     \
        FMA2(_a1, _v.y, rEa[2*_c+1], _a1);                                     \
        FMA2(_b1, _v.y, rEb[2*_c+1], _b1);                                     \
    }                                                                          \
    ADD2(_a0, _a0, _a1); ADD2(_b0, _b0, _b1);                                  \
    float _alo, _ahi, _blo, _bhi;                                              \
    UNPACK2(_alo, _ahi, _a0); UNPACK2(_blo, _bhi, _b0);                        \
    unsigned long long _sp; PACK2(_sp, _alo + _ahi, _blo + _bhi);              \
    unsigned long long _sv; MUL2(_sv, _sp, _emxs);                             \
    ((unsigned long long*)(QW))[l] = _sv;                                      \
    __syncwarp();                                                              \
} while (0)

__global__ __launch_bounds__(32, 1)
void crf_kernel(const float* __restrict__ em,
                const int*   __restrict__ tags,
                const float* __restrict__ mask,
                const float* __restrict__ U,
                float* __restrict__ out)
{
    const int b  = blockIdx.x;
    const int l  = threadIdx.x;          // 0..31
    const int j0 = 2 * l, j1 = 2 * l + 1;

    __shared__ __align__(16) float qA[Cc];
    __shared__ __align__(16) float qB[Cc];
    __shared__ __align__(16) float sU[Cc * Cc];
    __shared__ __align__(16) int   stags[Sc];
    __shared__ __align__(16) float smask[Sc];

    // ---- stage U (coalesced float4), tags, mask into smem ----
    {
        const float4* U4  = (const float4*)U;
        float4*       sU4 = (float4*)sU;
#pragma unroll
        for (int i = 0; i < (Cc * Cc / 4) / 32; ++i)     // 32 iters
            sU4[l + 32 * i] = U4[l + 32 * i];

        const int4*   t4  = (const int4*)(tags + (size_t)b * Sc);
        int4*         st4 = (int4*)stags;
        const float4* m4  = (const float4*)(mask + (size_t)b * Sc);
        float4*       sm4 = (float4*)smask;
#pragma unroll
        for (int i = 0; i < 2; ++i) {
            st4[l + 32 * i] = t4[l + 32 * i];
            sm4[l + 32 * i] = m4[l + 32 * i];
        }
    }
    __syncwarp();

    // ---- expU columns j0,j1 packed over i-pairs: 64 u64 registers ----
    unsigned long long rEa[32], rEb[32];
#pragma unroll
    for (int p = 0; p < 32; ++p) {
        float2 ra = *(const float2*)&sU[(2 * p + 0) * Cc + j0]; // {E[2p][j0],E[2p][j1]}
        float2 rb = *(const float2*)&sU[(2 * p + 1) * Cc + j0];
        float a0 = __expf(ra.x), a1 = __expf(rb.x);
        float b0e = __expf(ra.y), b1e = __expf(rb.y);
        PACK2(rEa[p], a0, a1);       // {E[2p][j0], E[2p+1][j0]}
        PACK2(rEb[p], b0e, b1e);     // {E[2p][j1], E[2p+1][j1]}
    }

    const float2* emb2 = (const float2*)(em + (size_t)b * Sc * Cc); // raw[t] = emb2[t*32+l]

    // mask uniformity check (hoists branch out of hot loop)
    int ok = 1;
#pragma unroll
    for (int t = l; t < Sc; t += 32) ok &= (smask[t] == 1.0f);
    ok = __all_sync(0xFFFFFFFFu, ok);

    // q(0) = exp(em[0])
    {
        float2 e0 = emb2[l];
        float  x0 = __expf(e0.x), x1 = __expf(e0.y);
        unsigned long long q0p; PACK2(q0p, x0, x1);
        ((unsigned long long*)qA)[l] = q0p;
    }
    int K = 0;
    __syncwarp();

    if (ok) {
        // ---- fast path: branch-free, deep prefetch ----
        float2 r1 = emb2[1 * 32 + l];
        float2 c2 = emb2[2 * 32 + l], c3 = emb2[3 * 32 + l];
        float2 c4 = emb2[4 * 32 + l], c5 = emb2[5 * 32 + l];
        float2 c6 = emb2[6 * 32 + l], c7 = emb2[7 * 32 + l];

        unsigned long long ex1; EXPF2(ex1, r1);     // for t=1
        unsigned long long ex0n; EXPF2(ex0n, c2);   // for t=2
        unsigned long long ex1n; EXPF2(ex1n, c3);   // for t=3

        STEP(qA, qB, ex1);                          // t = 1

        unsigned long long ex0 = ex0n, exo = ex1n;
        c2 = c4; c3 = c5; c4 = c6; c5 = c7;         // raw for t+2..t+5 at t=2

#pragma unroll 1
        for (int t = 2; t < Sc; t += 2) {
            float2 n6 = (t + 6 < Sc) ? emb2[(t + 6) * 32 + l] : make_float2(0.f, 0.f);
            float2 n7 = (t + 7 < Sc) ? emb2[(t + 7) * 32 + l] : make_float2(0.f, 0.f);
            unsigned long long exa; EXPF2(exa, c2); // for t+2
            unsigned long long exb; EXPF2(exb, c3); // for t+3

            STEP(qB, qA, ex0);                      // step t   (even)
            STEP(qA, qB, exo);                      // step t+1 (odd)

            ex0 = exa; exo = exb;
            c2 = c4; c3 = c5; c4 = n6; c5 = n7;
        }
        // final q in qB (t=255 odd)
    } else {
        // ---- generic masked fallback (never taken in this dataset) ----
        const float* qr = qA; float* qw = qB;
        for (int t = 1; t < Sc; ++t) {
            float  m   = smask[t];
            float2 emv = emb2[t * 32 + l];
            float  q0  = qr[0];
            int    k   = (int)((__float_as_uint(q0) >> 23) & 0xFF) - 127;
            float  sc  = __uint_as_float((unsigned)(127 - k) << 23);
            K += k;

            float s0, s1;
            if (m == 1.0f) {
                float a = 0.f, c = 0.f;
                for (int i = 0; i < Cc; ++i) {
                    float qi = qr[i];
                    a = fmaf(qi, __expf(sU[i * Cc + j0]), a);
                    c = fmaf(qi, __expf(sU[i * Cc + j1]), c);
                }
                s0 = a * __expf(emv.x);
                s1 = c * __expf(emv.y);
            } else if (m == 0.0f) {
                float a = 0.f;
                for (int i = 0; i < Cc; ++i) a += qr[i];
                s0 = s1 = a;
            } else {
                float a = 0.f, c = 0.f;
                for (int i = 0; i < Cc; ++i) {
                    a += qr[i] * __expf((emv.x + sU[i * Cc + j0]) * m);
                    c += qr[i] * __expf((emv.y + sU[i * Cc + j1]) * m);
                }
                s0 = a; s1 = c;
            }
            qw[j0] = s0 * sc;
            qw[j1] = s1 * sc;
            __syncwarp();
            const float* tr = qr; qr = qw; qw = const_cast<float*>(tr);
        }
        // t=255 (odd) wrote qB
    }

    // ---- path energy ----
    const float* embf = em + (size_t)b * Sc * Cc;
    float pe = 0.0f;
#pragma unroll
    for (int t = l; t < Sc; t += 32) {
        float mt = smask[t];
        int   tg = stags[t];
        int   tm = (int)((float)tg * mt);
        pe += embf[t * Cc + tm] * mt;
    }
#pragma unroll
    for (int t = 1 + l; t < Sc; t += 32) {
        pe += sU[stags[t - 1] * Cc + stags[t]] * smask[t];
    }
#pragma unroll
    for (int o = 16; o > 0; o >>= 1)
        pe += __shfl_xor_sync(0xFFFFFFFFu, pe, o);

    // ---- free energy + per-batch result ----
    if (l == 0) {
        float qs = 0.0f;
#pragma unroll
        for (int i = 0; i < Cc; ++i) qs += qB[i];
        float fe = logf(qs) + (float)K * 0.6931471805599453f;
        g_batch_res[b] = fe - pe;
        __threadfence();
    }

    // ---- fused finalize: last CTA computes the batch mean ----
    unsigned int old = 0;
    if (l == 0) old = atomicAdd(&g_ticket, 1u);
    old = __shfl_sync(0xFFFFFFFFu, old, 0);
    if (old == Bc - 1) {
        __threadfence();
        float v = 0.0f;
#pragma unroll
        for (int i = 0; i < Bc / 32; ++i) v += g_batch_res[l + 32 * i];
#pragma unroll
        for (int o = 16; o > 0; o >>= 1)
            v += __shfl_xor_sync(0xFFFFFFFFu, v, o);
        if (l == 0) {
            out[0] = v * (1.0f / (float)Bc);
            g_ticket = 0;                     // reset for next graph replay
        }
    }
}

extern "C" void kernel_launch(void* const* d_in, const int* in_sizes, int n_in,
                              void* d_out, int out_size)
{
    const float* emissions = (const float*)d_in[0];
    const int*   true_tags = (const int*)  d_in[1];
    const float* mask      = (const float*)d_in[2];
    const float* U         = (const float*)d_in[3];
    float* out = (float*)d_out;

    crf_kernel<<<Bc, 32>>>(emissions, true_tags, mask, U, out);
}

// round 7
// speedup vs baseline: 1.6501x; 1.2569x over previous
#include <cuda_runtime.h>
#include <cuda_bf16.h>
#include <math.h>

// ChainCRF: B=128, S=256, C=64.
// TWO WARPS per batch row (128 CTAs x 64 threads). Thread j owns column j.
// Linear-domain forward recursion, power-of-two renorm folded into the
// emission multiplier (off the critical chain), log taken once at the end.
// Per step per thread: 16 broadcast LDS.128 (q), 32 fma.rn.f32x2, STS.32,
// one __syncthreads. expU column lives in 32 u64 registers per thread.

#define Bc 128
#define Sc 256
#define Cc 64
#define Tc 64

__device__ float g_batch_res[Bc];
__device__ unsigned int g_ticket = 0;

#define FMA2(d,a,b,c)  asm("fma.rn.f32x2 %0, %1, %2, %3;" : "=l"(d) : "l"(a), "l"(b), "l"(c))
#define ADD2(d,a,b)    asm("add.rn.f32x2 %0, %1, %2;" : "=l"(d) : "l"(a), "l"(b))
#define PACK2(d,lo,hi) asm("mov.b64 %0, {%1, %2};" : "=l"(d) : "f"(lo), "f"(hi))
#define UNPACK2(lo,hi,s) asm("mov.b64 {%0, %1}, %2;" : "=f"(lo), "=f"(hi) : "l"(s))

// One forward step: q_new[j] = (sum_i q_i * expU[i][j]) * emx_j * scale
// QR/QW: 64-float smem buffers. EMX: float (already exp'd emission for col j).
#define STEP(QR, QW, EMX) do {                                                 \
    float _q0 = (QR)[0];                                                       \
    int   _k  = (int)((__float_as_uint(_q0) >> 23) & 0xFF) - 127;              \
    K += _k;                                                                   \
    float _emx = (EMX) * __uint_as_float((unsigned)(127 - _k) << 23);          \
    unsigned long long _a0 = 0ull, _a1 = 0ull;                                 \
    const ulonglong2* _qv = (const ulonglong2*)(QR);                           \
    _Pragma("unroll")                                                          \
    for (int _c = 0; _c < 16; ++_c) {                                          \
        ulonglong2 _v = _qv[_c];                                               \
        FMA2(_a0, _v.x, rE[2*_c+0], _a0);                                      \
        FMA2(_a1, _v.y, rE[2*_c+1], _a1);                                      \
    }                                                                          \
    ADD2(_a0, _a0, _a1);                                                       \
    float _lo, _hi;                                                            \
    UNPACK2(_lo, _hi, _a0);                                                    \
    (QW)[j] = (_lo + _hi) * _emx;                                              \
    __syncthreads();                                                           \
} while (0)

__global__ __launch_bounds__(Tc, 1)
void crf_kernel(const float* __restrict__ em,
                const int*   __restrict__ tags,
                const float* __restrict__ mask,
                const float* __restrict__ U,
                float* __restrict__ out)
{
    const int b = blockIdx.x;
    const int j = threadIdx.x;           // column owned by this thread (0..63)
    const int l = j & 31;                // lane
    const int w = j >> 5;                // warp (0,1)

    __shared__ __align__(16) float qA[Cc];
    __shared__ __align__(16) float qB[Cc];
    __shared__ __align__(16) float sU[Cc * Cc];
    __shared__ __align__(16) int   stags[Sc];
    __shared__ __align__(16) float smask[Sc];
    __shared__ float red[2];

    // ---- stage U, tags, mask into smem (coalesced float4/int4) ----
    {
        const float4* U4  = (const float4*)U;
        float4*       sU4 = (float4*)sU;
#pragma unroll
        for (int i = 0; i < (Cc * Cc / 4) / Tc; ++i)     // 16 iters
            sU4[j + Tc * i] = U4[j + Tc * i];

        const int4*   t4  = (const int4*)(tags + (size_t)b * Sc);
        const float4* m4  = (const float4*)(mask + (size_t)b * Sc);
        ((int4*)stags)[j]  = t4[j];
        ((float4*)smask)[j] = m4[j];
    }
    __syncthreads();

    // ---- expU column j packed over i-pairs: 32 u64 registers ----
    unsigned long long rE[32];
#pragma unroll
    for (int p = 0; p < 32; ++p) {
        float e0 = __expf(sU[(2 * p + 0) * Cc + j]);
        float e1 = __expf(sU[(2 * p + 1) * Cc + j]);
        PACK2(rE[p], e0, e1);            // {E[2p][j], E[2p+1][j]}
    }

    const float* emb = em + (size_t)b * Sc * Cc;   // em[t][j] = emb[t*64 + j]

    // mask uniformity check (hoists the branch out of the hot loop)
    int ok = 1;
#pragma unroll
    for (int t = j; t < Sc; t += Tc) ok &= (smask[t] == 1.0f);
    ok = __syncthreads_and(ok);

    // q(0) = exp(em[0])
    qA[j] = __expf(emb[j]);
    int K = 0;
    __syncthreads();

    if (ok) {
        // ---- fast path: branch-free, deep prefetch ----
        float r1 = emb[1 * Cc + j];
        float c2 = emb[2 * Cc + j], c3 = emb[3 * Cc + j];
        float c4 = emb[4 * Cc + j], c5 = emb[5 * Cc + j];
        float c6 = emb[6 * Cc + j], c7 = emb[7 * Cc + j];

        float ex1  = __expf(r1);         // for t=1
        float ex0n = __expf(c2);         // for t=2
        float ex1n = __expf(c3);         // for t=3

        STEP(qA, qB, ex1);               // t = 1

        float ex0 = ex0n, exo = ex1n;
        c2 = c4; c3 = c5; c4 = c6; c5 = c7;   // raw for t+2..t+5 at t=2

#pragma unroll 1
        for (int t = 2; t < Sc; t += 2) {
            float n6 = (t + 6 < Sc) ? emb[(t + 6) * Cc + j] : 0.0f;
            float n7 = (t + 7 < Sc) ? emb[(t + 7) * Cc + j] : 0.0f;
            float exa = __expf(c2);      // for t+2
            float exb = __expf(c3);      // for t+3

            STEP(qB, qA, ex0);           // step t   (even)
            STEP(qA, qB, exo);           // step t+1 (odd)

            ex0 = exa; exo = exb;
            c2 = c4; c3 = c5; c4 = n6; c5 = n7;
        }
        // t=255 (odd) wrote qB
    } else {
        // ---- generic masked fallback (never taken in this dataset) ----
        const float* qr = qA; float* qw = qB;
        for (int t = 1; t < Sc; ++t) {
            float m   = smask[t];
            float emv = emb[t * Cc + j];
            float q0  = qr[0];
            int   k   = (int)((__float_as_uint(q0) >> 23) & 0xFF) - 127;
            float sc  = __uint_as_float((unsigned)(127 - k) << 23);
            K += k;

            float s;
            if (m == 1.0f) {
                float a = 0.f;
                for (int i = 0; i < Cc; ++i)
                    a = fmaf(qr[i], __expf(sU[i * Cc + j]), a);
                s = a * __expf(emv);
            } else if (m == 0.0f) {
                float a = 0.f;
                for (int i = 0; i < Cc; ++i) a += qr[i];
                s = a;
            } else {
                float a = 0.f;
                for (int i = 0; i < Cc; ++i)
                    a += qr[i] * __expf((emv + sU[i * Cc + j]) * m);
                s = a;
            }
            qw[j] = s * sc;
            __syncthreads();
            const float* tr = qr; qr = qw; qw = const_cast<float*>(tr);
        }
        // t=255 (odd) wrote qB
    }

    // ---- path energy ----
    float pe = 0.0f;
#pragma unroll
    for (int t = j; t < Sc; t += Tc) {
        float mt = smask[t];
        int   tg = stags[t];
        int   tm = (int)((float)tg * mt);
        pe += emb[t * Cc + tm] * mt;
    }
#pragma unroll
    for (int t = 1 + j; t < Sc; t += Tc) {
        pe += sU[stags[t - 1] * Cc + stags[t]] * smask[t];
    }
#pragma unroll
    for (int o = 16; o > 0; o >>= 1)
        pe += __shfl_xor_sync(0xFFFFFFFFu, pe, o);
    if (l == 0) red[w] = pe;
    __syncthreads();

    // ---- free energy + per-batch result + fused finalize ----
    if (j == 0) {
        float qs = 0.0f;
#pragma unroll
        for (int i = 0; i < Cc; ++i) qs += qB[i];
        float fe = logf(qs) + (float)K * 0.6931471805599453f;
        g_batch_res[b] = fe - (red[0] + red[1]);
        __threadfence();
    }
    __syncthreads();

    if (w == 0) {
        unsigned int old = 0;
        if (l == 0) old = atomicAdd(&g_ticket, 1u);
        old = __shfl_sync(0xFFFFFFFFu, old, 0);
        if (old == Bc - 1) {
            __threadfence();
            float v = 0.0f;
#pragma unroll
            for (int i = 0; i < Bc / 32; ++i) v += g_batch_res[l + 32 * i];
#pragma unroll
            for (int o = 16; o > 0; o >>= 1)
                v += __shfl_xor_sync(0xFFFFFFFFu, v, o);
            if (l == 0) {
                out[0] = v * (1.0f / (float)Bc);
                g_ticket = 0;              // reset for next graph replay
            }
        }
    }
}

extern "C" void kernel_launch(void* const* d_in, const int* in_sizes, int n_in,
                              void* d_out, int out_size)
{
    const float* emissions = (const float*)d_in[0];
    const int*   true_tags = (const int*)  d_in[1];
    const float* mask      = (const float*)d_in[2];
    const float* U         = (const float*)d_in[3];
    float* out = (float*)d_out;

    crf_kernel<<<Bc, Tc>>>(emissions, true_tags, mask, U, out);
}